// round 4
// baseline (speedup 1.0000x reference)
#include <cuda_runtime.h>

#define B_  2
#define H_  12
#define S_  2048
#define D_  64
#define BR  64
#define BC  64
#define NT  256
#define STRIDE 68   // padded row stride for float tiles
#define PST 66      // padded row stride (in ull) for dup-packed P — MUST be even (16B align)

typedef unsigned long long ull;

__device__ int g_seg_start[B_ * S_];

__global__ void segstart_kernel(const int* __restrict__ block_ids) {
    int idx = blockIdx.x * blockDim.x + threadIdx.x;
    if (idx >= B_ * S_) return;
    int b = idx / S_, qpos = idx % S_;
    const int* bi = block_ids + b * S_;
    int val = bi[qpos];
    int lo = 0, hi = qpos;
    while (lo < hi) {
        int mid = (lo + hi) >> 1;
        if (bi[mid] < val) lo = mid + 1; else hi = mid;
    }
    g_seg_start[idx] = lo;
}

__device__ __forceinline__ ull fma2(ull a, ull b, ull c) {
    ull d;
    asm("fma.rn.f32x2 %0, %1, %2, %3;" : "=l"(d) : "l"(a), "l"(b), "l"(c));
    return d;
}
__device__ __forceinline__ ull pack2(float lo, float hi) {
    ull d;
    asm("mov.b64 %0, {%1, %2};" : "=l"(d) : "f"(lo), "f"(hi));
    return d;
}
__device__ __forceinline__ float2 unpack2(ull v) {
    float2 r;
    asm("mov.b64 {%0, %1}, %2;" : "=f"(r.x), "=f"(r.y) : "l"(v));
    return r;
}
__device__ __forceinline__ float ex2(float x) {
    float y;
    asm("ex2.approx.ftz.f32 %0, %1;" : "=f"(y) : "f"(x));
    return y;
}

extern __shared__ float smem[];

__global__ __launch_bounds__(NT, 2)
void attn_kernel(const float* __restrict__ Q, const float* __restrict__ K,
                 const float* __restrict__ V, float* __restrict__ O) {
    float* Qs = smem;                        // [BR][STRIDE], pre-scaled by 0.125*log2e
    float* Ks = Qs + BR * STRIDE;            // [BC][STRIDE] row-major
    float* Vs = Ks + BC * STRIDE;            // [BC][STRIDE] dim-permuted cols
    ull*   Ps = (ull*)(Vs + BC * STRIDE);    // [BC][PST] dup-packed, row-permuted

    const int qt = blockIdx.x, h = blockIdx.y, b = blockIdx.z;
    const int q0 = qt * BR;
    const long base = ((long)(b * H_ + h)) * S_ * D_;
    const float* Qb = Q + base + (long)q0 * D_;
    const float* Kb = K + base;
    const float* Vb = V + base;

    const int t  = threadIdx.x;
    const int tx = t & 15;       // col/dim group: owns cols tx+16j
    const int ty = t >> 4;       // row group: owns rows ty+16i

    // Load Q tile, pre-scaled so score_log2 = dot(Qs_row, K_col)
    const float QSCALE = 0.125f * 1.44269504088896340736f;
    #pragma unroll
    for (int u = 0; u < 4; u++) {
        int idx = t + NT * u;
        int r = idx >> 4, c4 = idx & 15;
        float4 qv = *(const float4*)&Qb[r * D_ + c4 * 4];
        qv.x *= QSCALE; qv.y *= QSCALE; qv.z *= QSCALE; qv.w *= QSCALE;
        *(float4*)&Qs[r * STRIDE + c4 * 4] = qv;
    }

    int st[4];
    #pragma unroll
    for (int i = 0; i < 4; i++) st[i] = g_seg_start[b * S_ + q0 + ty + 16 * i];
    const int kstart = (g_seg_start[b * S_ + q0] / BC) * BC;

    // Unstable ghost-softmax: p = exp(s) raw (bounded inputs), l = 1 + sum p.
    // Each thread holds a partial l; ghost's +1 contributed by tx==0 lanes only.
    float l[4];
    #pragma unroll
    for (int i = 0; i < 4; i++) l[i] = (tx == 0) ? 1.f : 0.f;
    ull oacc[4][2];
    #pragma unroll
    for (int i = 0; i < 4; i++) { oacc[i][0] = 0ull; oacc[i][1] = 0ull; }

    for (int kt = kstart; kt <= q0; kt += BC) {
        __syncthreads();   // previous iteration's K/V/P readers done

        // Load K (row-major) and V (dim-permuted: dim d -> col (d&15)*4 + (d>>4))
        #pragma unroll
        for (int u = 0; u < 4; u++) {
            int idx = t + NT * u;
            int r = idx >> 4, c4 = idx & 15;
            *(float4*)&Ks[r * STRIDE + c4 * 4] =
                *(const float4*)&Kb[(long)(kt + r) * D_ + c4 * 4];
            float4 vv = *(const float4*)&Vb[(long)(kt + r) * D_ + c4 * 4];
            int d0 = c4 * 4;
            Vs[r * STRIDE + ((d0 + 0) & 15) * 4 + ((d0 + 0) >> 4)] = vv.x;
            Vs[r * STRIDE + ((d0 + 1) & 15) * 4 + ((d0 + 1) >> 4)] = vv.y;
            Vs[r * STRIDE + ((d0 + 2) & 15) * 4 + ((d0 + 2) >> 4)] = vv.z;
            Vs[r * STRIDE + ((d0 + 3) & 15) * 4 + ((d0 + 3) >> 4)] = vv.w;
        }
        __syncthreads();

        // ---- QK: 4x4 fragment, packed f32x2 accumulation over d ----
        ull acc[4][4];
        #pragma unroll
        for (int i = 0; i < 4; i++)
            #pragma unroll
            for (int j = 0; j < 4; j++) acc[i][j] = 0ull;

        #pragma unroll 4
        for (int d4 = 0; d4 < 16; d4++) {
            ulonglong2 qp[4];
            #pragma unroll
            for (int i = 0; i < 4; i++)
                qp[i] = *(ulonglong2*)&Qs[(ty + 16 * i) * STRIDE + d4 * 4];
            #pragma unroll
            for (int j = 0; j < 4; j++) {
                ulonglong2 kp = *(ulonglong2*)&Ks[(tx + 16 * j) * STRIDE + d4 * 4];
                #pragma unroll
                for (int i = 0; i < 4; i++) {
                    acc[i][j] = fma2(qp[i].x, kp.x, acc[i][j]);
                    acc[i][j] = fma2(qp[i].y, kp.y, acc[i][j]);
                }
            }
        }

        // ---- mask + exp2, accumulate partial l, dup-pack P ----
        ull pp[4][4];
        #pragma unroll
        for (int i = 0; i < 4; i++) {
            int rg = q0 + ty + 16 * i;
            float pi[4];
            #pragma unroll
            for (int j = 0; j < 4; j++) {
                float2 f = unpack2(acc[i][j]);
                float s = f.x + f.y;               // already in log2 units
                int cg = kt + tx + 16 * j;
                bool in = (cg >= st[i]) & (cg <= rg);
                pi[j] = in ? ex2(s) : 0.f;
            }
            l[i] += (pi[0] + pi[1]) + (pi[2] + pi[3]);
            #pragma unroll
            for (int j = 0; j < 4; j++) pp[i][j] = pack2(pi[j], pi[j]);
        }

        // store P dup-packed, row-permuted: row (ty+16i) -> slot ty*4+i
        #pragma unroll
        for (int j = 0; j < 4; j++) {
            ull* dst = &Ps[(tx + 16 * j) * PST + ty * 4];
            *(ulonglong2*)&dst[0] = make_ulonglong2(pp[0][j], pp[1][j]);
            *(ulonglong2*)&dst[2] = make_ulonglong2(pp[2][j], pp[3][j]);
        }
        __syncthreads();

        // ---- PV: per key, 3 LDS.128 + 8 FFMA2, zero MOVs ----
        #pragma unroll 8
        for (int k = 0; k < BC; k++) {
            ulonglong2 pA = *(ulonglong2*)&Ps[k * PST + ty * 4];      // rows i=0,1
            ulonglong2 pB = *(ulonglong2*)&Ps[k * PST + ty * 4 + 2];  // rows i=2,3
            ulonglong2 vf = *(ulonglong2*)&Vs[k * STRIDE + tx * 4];
            oacc[0][0] = fma2(pA.x, vf.x, oacc[0][0]);
            oacc[0][1] = fma2(pA.x, vf.y, oacc[0][1]);
            oacc[1][0] = fma2(pA.y, vf.x, oacc[1][0]);
            oacc[1][1] = fma2(pA.y, vf.y, oacc[1][1]);
            oacc[2][0] = fma2(pB.x, vf.x, oacc[2][0]);
            oacc[2][1] = fma2(pB.x, vf.y, oacc[2][1]);
            oacc[3][0] = fma2(pB.y, vf.x, oacc[3][0]);
            oacc[3][1] = fma2(pB.y, vf.y, oacc[3][1]);
        }
    }

    // final l reduction across the 16 lanes owning each row, then write out
    #pragma unroll
    for (int i = 0; i < 4; i++) {
        float ls = l[i];
        #pragma unroll
        for (int off = 1; off < 16; off <<= 1)
            ls += __shfl_xor_sync(0xffffffffu, ls, off);
        float inv = 1.f / ls;
        int row = q0 + ty + 16 * i;
        float* op = (float*)O + base + (long)row * D_;
        float2 o0 = unpack2(oacc[i][0]);
        float2 o1 = unpack2(oacc[i][1]);
        op[tx]      = o0.x * inv;
        op[tx + 16] = o0.y * inv;
        op[tx + 32] = o1.x * inv;
        op[tx + 48] = o1.y * inv;
    }
}

extern "C" void kernel_launch(void* const* d_in, const int* in_sizes, int n_in,
                              void* d_out, int out_size) {
    const float* q  = (const float*)d_in[0];
    const float* k  = (const float*)d_in[1];
    const float* v  = (const float*)d_in[2];
    const int* bids = (const int*)d_in[3];
    float* out      = (float*)d_out;

    segstart_kernel<<<(B_ * S_ + 255) / 256, 256>>>(bids);

    const int smem_bytes = 3 * BC * STRIDE * (int)sizeof(float)
                         + BC * PST * (int)sizeof(ull);   // 52224 + 33792 = 86016
    cudaFuncSetAttribute(attn_kernel, cudaFuncAttributeMaxDynamicSharedMemorySize,
                         smem_bytes);
    dim3 grid(S_ / BR, H_, B_);
    attn_kernel<<<grid, NT, smem_bytes>>>(q, k, v, out);
}

// round 5
// speedup vs baseline: 1.1605x; 1.1605x over previous
#include <cuda_runtime.h>

#define B_  2
#define H_  12
#define S_  2048
#define D_  64
#define BR  64
#define BC  64
#define NT  256
#define STRIDE 68   // padded row stride (floats) for all tiles

typedef unsigned long long ull;

__device__ int g_seg_start[B_ * S_];

__global__ void segstart_kernel(const int* __restrict__ block_ids) {
    int idx = blockIdx.x * blockDim.x + threadIdx.x;
    if (idx >= B_ * S_) return;
    int b = idx / S_, qpos = idx % S_;
    const int* bi = block_ids + b * S_;
    int val = bi[qpos];
    int lo = 0, hi = qpos;
    while (lo < hi) {
        int mid = (lo + hi) >> 1;
        if (bi[mid] < val) lo = mid + 1; else hi = mid;
    }
    g_seg_start[idx] = lo;
}

__device__ __forceinline__ ull fma2(ull a, ull b, ull c) {
    ull d;
    asm("fma.rn.f32x2 %0, %1, %2, %3;" : "=l"(d) : "l"(a), "l"(b), "l"(c));
    return d;
}
__device__ __forceinline__ ull pack2(float lo, float hi) {
    ull d;
    asm("mov.b64 %0, {%1, %2};" : "=l"(d) : "f"(lo), "f"(hi));
    return d;
}
__device__ __forceinline__ float2 unpack2(ull v) {
    float2 r;
    asm("mov.b64 {%0, %1}, %2;" : "=f"(r.x), "=f"(r.y) : "l"(v));
    return r;
}
__device__ __forceinline__ float ex2(float x) {
    float y;
    asm("ex2.approx.ftz.f32 %0, %1;" : "=f"(y) : "f"(x));
    return y;
}

extern __shared__ float smem[];

__global__ __launch_bounds__(NT, 2)
void attn_kernel(const float* __restrict__ Q, const float* __restrict__ K,
                 const float* __restrict__ V, float* __restrict__ O) {
    float* Qs = smem;                        // [BR][STRIDE], pre-scaled by 0.125*log2e
    float* Ks = Qs + BR * STRIDE;            // [BC][STRIDE] row-major
    float* Vs = Ks + BC * STRIDE;            // [BC][STRIDE] row-major
    float* Ps = Vs + BC * STRIDE;            // [BC][STRIDE] row-permuted float P

    const int qt = blockIdx.x, h = blockIdx.y, b = blockIdx.z;
    const int q0 = qt * BR;
    const long base = ((long)(b * H_ + h)) * S_ * D_;
    const float* Qb = Q + base + (long)q0 * D_;
    const float* Kb = K + base;
    const float* Vb = V + base;

    const int t  = threadIdx.x;
    const int tx = t & 15;       // QK col group: cols tx+16j; PV dims [4tx,4tx+4)
    const int ty = t >> 4;       // row group: rows ty+16i

    // Load Q tile, pre-scaled so score in log2 units = dot(Qs_row, K_col)
    const float QSCALE = 0.125f * 1.44269504088896340736f;
    #pragma unroll
    for (int u = 0; u < 4; u++) {
        int idx = t + NT * u;
        int r = idx >> 4, c4 = idx & 15;
        float4 qv = *(const float4*)&Qb[r * D_ + c4 * 4];
        qv.x *= QSCALE; qv.y *= QSCALE; qv.z *= QSCALE; qv.w *= QSCALE;
        *(float4*)&Qs[r * STRIDE + c4 * 4] = qv;
    }

    int st[4];
    #pragma unroll
    for (int i = 0; i < 4; i++) st[i] = g_seg_start[b * S_ + q0 + ty + 16 * i];
    const int kstart = (g_seg_start[b * S_ + q0] / BC) * BC;

    // Unstable ghost-softmax: p = exp2(s_log2) raw (bounded inputs), l = 1 + sum p.
    float l[4];
    #pragma unroll
    for (int i = 0; i < 4; i++) l[i] = (tx == 0) ? 1.f : 0.f;
    ull oacc[4][2];   // [row i][dim pair]: (4tx,4tx+1) and (4tx+2,4tx+3)
    #pragma unroll
    for (int i = 0; i < 4; i++) { oacc[i][0] = 0ull; oacc[i][1] = 0ull; }

    for (int kt = kstart; kt <= q0; kt += BC) {
        __syncthreads();   // previous iteration's K/V/P readers done

        // Load K and V tiles (both row-major, plain float4 stores)
        #pragma unroll
        for (int u = 0; u < 4; u++) {
            int idx = t + NT * u;
            int r = idx >> 4, c4 = idx & 15;
            *(float4*)&Ks[r * STRIDE + c4 * 4] =
                *(const float4*)&Kb[(long)(kt + r) * D_ + c4 * 4];
            *(float4*)&Vs[r * STRIDE + c4 * 4] =
                *(const float4*)&Vb[(long)(kt + r) * D_ + c4 * 4];
        }
        __syncthreads();

        // ---- QK: 4x4 fragment, packed f32x2 accumulation over d ----
        ull acc[4][4];
        #pragma unroll
        for (int i = 0; i < 4; i++)
            #pragma unroll
            for (int j = 0; j < 4; j++) acc[i][j] = 0ull;

        #pragma unroll 4
        for (int d4 = 0; d4 < 16; d4++) {
            ulonglong2 qp[4];
            #pragma unroll
            for (int i = 0; i < 4; i++)
                qp[i] = *(ulonglong2*)&Qs[(ty + 16 * i) * STRIDE + d4 * 4];
            #pragma unroll
            for (int j = 0; j < 4; j++) {
                ulonglong2 kp = *(ulonglong2*)&Ks[(tx + 16 * j) * STRIDE + d4 * 4];
                #pragma unroll
                for (int i = 0; i < 4; i++) {
                    acc[i][j] = fma2(qp[i].x, kp.x, acc[i][j]);
                    acc[i][j] = fma2(qp[i].y, kp.y, acc[i][j]);
                }
            }
        }

        // ---- mask + exp2, accumulate partial l ----
        float pr[4][4];
        #pragma unroll
        for (int i = 0; i < 4; i++) {
            int rg = q0 + ty + 16 * i;
            #pragma unroll
            for (int j = 0; j < 4; j++) {
                float2 f = unpack2(acc[i][j]);
                float s = f.x + f.y;               // log2 units
                int cg = kt + tx + 16 * j;
                bool in = (cg >= st[i]) & (cg <= rg);
                pr[i][j] = in ? ex2(s) : 0.f;
            }
            l[i] += (pr[i][0] + pr[i][1]) + (pr[i][2] + pr[i][3]);
        }

        // store P row-permuted: row (ty+16i) -> slot ty*4+i (one float4 per col)
        #pragma unroll
        for (int j = 0; j < 4; j++) {
            float4 w = make_float4(pr[0][j], pr[1][j], pr[2][j], pr[3][j]);
            *(float4*)&Ps[(tx + 16 * j) * STRIDE + ty * 4] = w;
        }
        __syncthreads();

        // ---- PV: per key, 2 LDS.128 (P broadcast + V) + 4 MOV + 8 FFMA2 ----
        #pragma unroll 8
        for (int k = 0; k < BC; k++) {
            float4 pf = *(float4*)&Ps[k * STRIDE + ty * 4];
            ulonglong2 vf = *(ulonglong2*)&Vs[k * STRIDE + tx * 4];
            ull pb0 = pack2(pf.x, pf.x);
            ull pb1 = pack2(pf.y, pf.y);
            ull pb2 = pack2(pf.z, pf.z);
            ull pb3 = pack2(pf.w, pf.w);
            oacc[0][0] = fma2(pb0, vf.x, oacc[0][0]);
            oacc[0][1] = fma2(pb0, vf.y, oacc[0][1]);
            oacc[1][0] = fma2(pb1, vf.x, oacc[1][0]);
            oacc[1][1] = fma2(pb1, vf.y, oacc[1][1]);
            oacc[2][0] = fma2(pb2, vf.x, oacc[2][0]);
            oacc[2][1] = fma2(pb2, vf.y, oacc[2][1]);
            oacc[3][0] = fma2(pb3, vf.x, oacc[3][0]);
            oacc[3][1] = fma2(pb3, vf.y, oacc[3][1]);
        }
    }

    // final l reduction over the 16 lanes owning each row; contiguous float4 out
    #pragma unroll
    for (int i = 0; i < 4; i++) {
        float ls = l[i];
        #pragma unroll
        for (int off = 1; off < 16; off <<= 1)
            ls += __shfl_xor_sync(0xffffffffu, ls, off);
        float inv = 1.f / ls;
        int row = q0 + ty + 16 * i;
        float* op = (float*)O + base + (long)row * D_ + 4 * tx;
        float2 o0 = unpack2(oacc[i][0]);
        float2 o1 = unpack2(oacc[i][1]);
        *(float4*)op = make_float4(o0.x * inv, o0.y * inv, o1.x * inv, o1.y * inv);
    }
}

extern "C" void kernel_launch(void* const* d_in, const int* in_sizes, int n_in,
                              void* d_out, int out_size) {
    const float* q  = (const float*)d_in[0];
    const float* k  = (const float*)d_in[1];
    const float* v  = (const float*)d_in[2];
    const int* bids = (const int*)d_in[3];
    float* out      = (float*)d_out;

    segstart_kernel<<<(B_ * S_ + 255) / 256, 256>>>(bids);

    const int smem_bytes = 4 * BC * STRIDE * (int)sizeof(float);  // 69632
    cudaFuncSetAttribute(attn_kernel, cudaFuncAttributeMaxDynamicSharedMemorySize,
                         smem_bytes);
    dim3 grid(S_ / BR, H_, B_);
    attn_kernel<<<grid, NT, smem_bytes>>>(q, k, v, out);
}

// round 7
// speedup vs baseline: 1.1653x; 1.0041x over previous
#include <cuda_runtime.h>

#define B_  2
#define H_  12
#define S_  2048
#define D_  64
#define BR  64
#define BC  64
#define NT  256
#define STRIDE 68   // padded row stride (floats) for all tiles

typedef unsigned long long ull;
typedef unsigned int u32;

__device__ int g_seg_start[B_ * S_];

__global__ void segstart_kernel(const int* __restrict__ block_ids) {
    int idx = blockIdx.x * blockDim.x + threadIdx.x;
    if (idx >= B_ * S_) return;
    int b = idx / S_, qpos = idx % S_;
    const int* bi = block_ids + b * S_;
    int val = bi[qpos];
    int lo = 0, hi = qpos;
    while (lo < hi) {
        int mid = (lo + hi) >> 1;
        if (bi[mid] < val) lo = mid + 1; else hi = mid;
    }
    g_seg_start[idx] = lo;
}

__device__ __forceinline__ ull fma2(ull a, ull b, ull c) {
    ull d;
    asm("fma.rn.f32x2 %0, %1, %2, %3;" : "=l"(d) : "l"(a), "l"(b), "l"(c));
    return d;
}
__device__ __forceinline__ ull pack2(float lo, float hi) {
    ull d;
    asm("mov.b64 %0, {%1, %2};" : "=l"(d) : "f"(lo), "f"(hi));
    return d;
}
__device__ __forceinline__ float2 unpack2(ull v) {
    float2 r;
    asm("mov.b64 {%0, %1}, %2;" : "=f"(r.x), "=f"(r.y) : "l"(v));
    return r;
}
__device__ __forceinline__ float ex2f(float x) {
    float y;
    asm("ex2.approx.ftz.f32 %0, %1;" : "=f"(y) : "f"(x));
    return y;
}
__device__ __forceinline__ u32 smem_u32(const void* p) {
    u32 a;
    asm("{ .reg .u64 t; cvta.to.shared.u64 t, %1; cvt.u32.u64 %0, t; }"
        : "=r"(a) : "l"(p));
    return a;
}
__device__ __forceinline__ void cp16(u32 dst, const void* src) {
    asm volatile("cp.async.cg.shared.global [%0], [%1], 16;"
                 :: "r"(dst), "l"(src) : "memory");
}
#define CP_COMMIT() asm volatile("cp.async.commit_group;" ::: "memory")
#define CP_WAIT0()  asm volatile("cp.async.wait_group 0;" ::: "memory")

extern __shared__ float smem[];

__global__ __launch_bounds__(NT, 2)
void attn_kernel(const float* __restrict__ Q, const float* __restrict__ K,
                 const float* __restrict__ V, float* __restrict__ O) {
    float* Qs = smem;                       // [BR][STRIDE], pre-scaled
    float* Ps = Qs + BR * STRIDE;           // [BC][STRIDE] row-permuted P
    float* KV = Ps + BC * STRIDE;           // 2 x (K tile, V tile)
    const int TILE = BC * STRIDE;

    const int qt = blockIdx.x, h = blockIdx.y, b = blockIdx.z;
    const int q0 = qt * BR;
    const long base = ((long)(b * H_ + h)) * S_ * D_;
    const float* Qb = Q + base + (long)q0 * D_;
    const float* Kb = K + base;
    const float* Vb = V + base;

    const int t  = threadIdx.x;
    const int tx = t & 15;       // QK col group: cols tx+16j; PV dims [4tx,4tx+4)
    const int ty = t >> 4;       // row group: rows ty+16i

    // per-thread copy slice coordinates (16B chunks)
    const int cr[4]  = { (t + 0*NT) >> 4, (t + 1*NT) >> 4, (t + 2*NT) >> 4, (t + 3*NT) >> 4 };
    const int cc4    = t & 15;
    const u32 kv_s   = smem_u32(KV);

    const int st0 = g_seg_start[b * S_ + q0];
    const int kstart = (st0 / BC) * BC;

    // ---- prologue: prefetch first K/V tile into buffer 0 ----
    {
        u32 kd = kv_s;
        u32 vd = kv_s + TILE * 4;
        #pragma unroll
        for (int u = 0; u < 4; u++) {
            u32 off = (u32)(cr[u] * STRIDE + cc4 * 4) * 4;
            cp16(kd + off, &Kb[(long)(kstart + cr[u]) * D_ + cc4 * 4]);
            cp16(vd + off, &Vb[(long)(kstart + cr[u]) * D_ + cc4 * 4]);
        }
        CP_COMMIT();
    }

    // ---- load Q tile, pre-scaled so score (log2 units) = dot(Qs_row, K_col) ----
    const float QSCALE = 0.125f * 1.44269504088896340736f;
    #pragma unroll
    for (int u = 0; u < 4; u++) {
        int idx = t + NT * u;
        int r = idx >> 4, c4 = idx & 15;
        float4 qv = *(const float4*)&Qb[r * D_ + c4 * 4];
        qv.x *= QSCALE; qv.y *= QSCALE; qv.z *= QSCALE; qv.w *= QSCALE;
        *(float4*)&Qs[r * STRIDE + c4 * 4] = qv;
    }

    int st[4];
    #pragma unroll
    for (int i = 0; i < 4; i++) st[i] = g_seg_start[b * S_ + q0 + ty + 16 * i];

    // Unstable ghost-softmax (validated r5): p = exp2(s) raw, l = 1 + sum p.
    float l[4];
    #pragma unroll
    for (int i = 0; i < 4; i++) l[i] = (tx == 0) ? 1.f : 0.f;
    ull oacc[4][2];
    #pragma unroll
    for (int i = 0; i < 4; i++) { oacc[i][0] = 0ull; oacc[i][1] = 0ull; }

    int buf = 0;
    for (int kt = kstart; kt <= q0; kt += BC, buf ^= 1) {
        float* Ks = KV + buf * (2 * TILE);
        float* Vs = Ks + TILE;

        CP_WAIT0();        // my chunks of tile(kt) arrived
        __syncthreads();   // everyone's chunks visible + PV(kt-BC) readers done

        // ---- QK: 4x4 fragment, packed f32x2 accumulation over d ----
        ull acc[4][4];
        #pragma unroll
        for (int i = 0; i < 4; i++)
            #pragma unroll
            for (int j = 0; j < 4; j++) acc[i][j] = 0ull;

        #pragma unroll 4
        for (int d4 = 0; d4 < 16; d4++) {
            ulonglong2 qp[4];
            #pragma unroll
            for (int i = 0; i < 4; i++)
                qp[i] = *(ulonglong2*)&Qs[(ty + 16 * i) * STRIDE + d4 * 4];
            #pragma unroll
            for (int j = 0; j < 4; j++) {
                ulonglong2 kp = *(ulonglong2*)&Ks[(tx + 16 * j) * STRIDE + d4 * 4];
                #pragma unroll
                for (int i = 0; i < 4; i++) {
                    acc[i][j] = fma2(qp[i].x, kp.x, acc[i][j]);
                    acc[i][j] = fma2(qp[i].y, kp.y, acc[i][j]);
                }
            }
        }

        // ---- mask + exp2, accumulate partial l ----
        float pr[4][4];
        #pragma unroll
        for (int i = 0; i < 4; i++) {
            int rg = q0 + ty + 16 * i;
            #pragma unroll
            for (int j = 0; j < 4; j++) {
                float2 f = unpack2(acc[i][j]);
                float s = f.x + f.y;               // log2 units
                int cg = kt + tx + 16 * j;
                bool in = (cg >= st[i]) & (cg <= rg);
                pr[i][j] = in ? ex2f(s) : 0.f;
            }
            l[i] += (pr[i][0] + pr[i][1]) + (pr[i][2] + pr[i][3]);
        }

        // store P row-permuted: row (ty+16i) -> slot ty*4+i
        #pragma unroll
        for (int j = 0; j < 4; j++) {
            float4 w = make_float4(pr[0][j], pr[1][j], pr[2][j], pr[3][j]);
            *(float4*)&Ps[(tx + 16 * j) * STRIDE + ty * 4] = w;
        }
        __syncthreads();   // P visible; buf^1 provably dead (idle since last sync)

        // ---- prefetch next tile into buf^1, overlapped with PV ----
        if (kt + BC <= q0) {
            u32 kd = kv_s + (buf ^ 1) * (2 * TILE) * 4;
            u32 vd = kd + TILE * 4;
            #pragma unroll
            for (int u = 0; u < 4; u++) {
                u32 off = (u32)(cr[u] * STRIDE + cc4 * 4) * 4;
                cp16(kd + off, &Kb[(long)(kt + BC + cr[u]) * D_ + cc4 * 4]);
                cp16(vd + off, &Vb[(long)(kt + BC + cr[u]) * D_ + cc4 * 4]);
            }
            CP_COMMIT();
        }

        // ---- PV: per key, 2 LDS.128 (P broadcast + V) + 4 MOV + 8 FFMA2 ----
        #pragma unroll 8
        for (int k = 0; k < BC; k++) {
            float4 pf = *(float4*)&Ps[k * STRIDE + ty * 4];
            ulonglong2 vf = *(ulonglong2*)&Vs[k * STRIDE + tx * 4];
            ull pb0 = pack2(pf.x, pf.x);
            ull pb1 = pack2(pf.y, pf.y);
            ull pb2 = pack2(pf.z, pf.z);
            ull pb3 = pack2(pf.w, pf.w);
            oacc[0][0] = fma2(pb0, vf.x, oacc[0][0]);
            oacc[0][1] = fma2(pb0, vf.y, oacc[0][1]);
            oacc[1][0] = fma2(pb1, vf.x, oacc[1][0]);
            oacc[1][1] = fma2(pb1, vf.y, oacc[1][1]);
            oacc[2][0] = fma2(pb2, vf.x, oacc[2][0]);
            oacc[2][1] = fma2(pb2, vf.y, oacc[2][1]);
            oacc[3][0] = fma2(pb3, vf.x, oacc[3][0]);
            oacc[3][1] = fma2(pb3, vf.y, oacc[3][1]);
        }
    }

    // final l reduction over the 16 lanes owning each row; contiguous float4 out
    #pragma unroll
    for (int i = 0; i < 4; i++) {
        float ls = l[i];
        #pragma unroll
        for (int off = 1; off < 16; off <<= 1)
            ls += __shfl_xor_sync(0xffffffffu, ls, off);
        float inv = 1.f / ls;
        int row = q0 + ty + 16 * i;
        float* op = (float*)O + base + (long)row * D_ + 4 * tx;
        float2 o0 = unpack2(oacc[i][0]);
        float2 o1 = unpack2(oacc[i][1]);
        *(float4*)op = make_float4(o0.x * inv, o0.y * inv, o1.x * inv, o1.y * inv);
    }
}

extern "C" void kernel_launch(void* const* d_in, const int* in_sizes, int n_in,
                              void* d_out, int out_size) {
    const float* q  = (const float*)d_in[0];
    const float* k  = (const float*)d_in[1];
    const float* v  = (const float*)d_in[2];
    const int* bids = (const int*)d_in[3];
    float* out      = (float*)d_out;

    segstart_kernel<<<(B_ * S_ + 255) / 256, 256>>>(bids);

    const int smem_bytes = 6 * BC * STRIDE * (int)sizeof(float);  // 104448
    cudaFuncSetAttribute(attn_kernel, cudaFuncAttributeMaxDynamicSharedMemorySize,
                         smem_bytes);
    dim3 grid(S_ / BR, H_, B_);
    attn_kernel<<<grid, NT, smem_bytes>>>(q, k, v, out);
}

// round 8
// speedup vs baseline: 1.3414x; 1.1511x over previous
#include <cuda_runtime.h>

#define B_  2
#define H_  12
#define S_  2048
#define D_  64
#define BR  64
#define BC  64
#define NT  256
#define STRIDE 68
#define NITEMS ((S_ / BR) * H_ * B_)   // 768
#define NCTAS  304

typedef unsigned long long ull;
typedef unsigned int u32;

__device__ int g_seg_start[B_ * S_];
__device__ u32 g_ctr;

__global__ void segstart_kernel(const int* __restrict__ block_ids) {
    int idx = blockIdx.x * blockDim.x + threadIdx.x;
    if (idx == 0) g_ctr = 0u;
    if (idx >= B_ * S_) return;
    int b = idx / S_, qpos = idx % S_;
    const int* bi = block_ids + b * S_;
    int val = bi[qpos];
    int lo = 0, hi = qpos;
    while (lo < hi) {
        int mid = (lo + hi) >> 1;
        if (bi[mid] < val) lo = mid + 1; else hi = mid;
    }
    g_seg_start[idx] = lo;
}

__device__ __forceinline__ ull fma2(ull a, ull b, ull c) {
    ull d;
    asm("fma.rn.f32x2 %0, %1, %2, %3;" : "=l"(d) : "l"(a), "l"(b), "l"(c));
    return d;
}
__device__ __forceinline__ ull pack2(float lo, float hi) {
    ull d;
    asm("mov.b64 %0, {%1, %2};" : "=l"(d) : "f"(lo), "f"(hi));
    return d;
}
__device__ __forceinline__ float2 unpack2(ull v) {
    float2 r;
    asm("mov.b64 {%0, %1}, %2;" : "=f"(r.x), "=f"(r.y) : "l"(v));
    return r;
}
__device__ __forceinline__ float ex2f(float x) {
    float y;
    asm("ex2.approx.ftz.f32 %0, %1;" : "=f"(y) : "f"(x));
    return y;
}
__device__ __forceinline__ u32 smem_u32(const void* p) {
    u32 a;
    asm("{ .reg .u64 t; cvta.to.shared.u64 t, %1; cvt.u32.u64 %0, t; }"
        : "=r"(a) : "l"(p));
    return a;
}
__device__ __forceinline__ void cp16(u32 dst, const void* src) {
    asm volatile("cp.async.cg.shared.global [%0], [%1], 16;"
                 :: "r"(dst), "l"(src) : "memory");
}
#define CP_COMMIT() asm volatile("cp.async.commit_group;" ::: "memory")
#define CP_WAIT0()  asm volatile("cp.async.wait_group 0;" ::: "memory")

extern __shared__ float smem[];

__global__ __launch_bounds__(NT, 2)
void attn_kernel(const float* __restrict__ Q, const float* __restrict__ K,
                 const float* __restrict__ V, float* __restrict__ O) {
    float* Qs = smem;                       // [BR][STRIDE], pre-scaled
    float* Ps = Qs + BR * STRIDE;           // [BC][STRIDE] row-permuted P
    float* KV = Ps + BC * STRIDE;           // 2 x (K tile, V tile)
    const int TILE = BC * STRIDE;
    __shared__ int s_item;

    const int t  = threadIdx.x;
    const int tx = t & 15;       // QK cols tx+16j; PV dims [4tx,4tx+4)
    const int ty = t >> 4;       // rows ty+16i

    const int cr[4]  = { (t + 0*NT) >> 4, (t + 1*NT) >> 4, (t + 2*NT) >> 4, (t + 3*NT) >> 4 };
    const int cc4    = t & 15;
    const u32 kv_s   = smem_u32(KV);
    const float QSCALE = 0.125f * 1.44269504088896340736f;

    for (;;) {
        if (t == 0) s_item = (int)atomicAdd(&g_ctr, 1u);
        __syncthreads();          // broadcast item; also fences prev item's smem use
        const int w = s_item;
        if (w >= NITEMS) return;

        // heavy-first heuristic: descending query-tile index
        const int qt = (S_ / BR - 1) - w / (B_ * H_);
        const int hb = w % (B_ * H_);
        const int h = hb % H_, b = hb / H_;

        const int q0 = qt * BR;
        const long base = ((long)(b * H_ + h)) * S_ * D_;
        const float* Qb = Q + base + (long)q0 * D_;
        const float* Kb = K + base;
        const float* Vb = V + base;

        const int kstart = (g_seg_start[b * S_ + q0] / BC) * BC;

        // prologue: prefetch first K/V tile into buffer 0
        {
            u32 kd = kv_s;
            u32 vd = kv_s + TILE * 4;
            #pragma unroll
            for (int u = 0; u < 4; u++) {
                u32 off = (u32)(cr[u] * STRIDE + cc4 * 4) * 4;
                cp16(kd + off, &Kb[(long)(kstart + cr[u]) * D_ + cc4 * 4]);
                cp16(vd + off, &Vb[(long)(kstart + cr[u]) * D_ + cc4 * 4]);
            }
            CP_COMMIT();
        }

        // load Q tile (pre-scaled: scores come out in log2 units)
        #pragma unroll
        for (int u = 0; u < 4; u++) {
            int idx = t + NT * u;
            int r = idx >> 4, c4 = idx & 15;
            float4 qv = *(const float4*)&Qb[r * D_ + c4 * 4];
            qv.x *= QSCALE; qv.y *= QSCALE; qv.z *= QSCALE; qv.w *= QSCALE;
            *(float4*)&Qs[r * STRIDE + c4 * 4] = qv;
        }

        int st[4];
        #pragma unroll
        for (int i = 0; i < 4; i++) st[i] = g_seg_start[b * S_ + q0 + ty + 16 * i];

        float l[4];
        #pragma unroll
        for (int i = 0; i < 4; i++) l[i] = (tx == 0) ? 1.f : 0.f;
        ull oacc[4][2];
        #pragma unroll
        for (int i = 0; i < 4; i++) { oacc[i][0] = 0ull; oacc[i][1] = 0ull; }

        int buf = 0;
        for (int kt = kstart; kt <= q0; kt += BC, buf ^= 1) {
            float* Ks = KV + buf * (2 * TILE);
            float* Vs = Ks + TILE;

            CP_WAIT0();
            __syncthreads();   // KV(kt) visible; everyone past previous tile

            // QK: 4x4 fragment, f32x2 accumulation over d
            ull acc[4][4];
            #pragma unroll
            for (int i = 0; i < 4; i++)
                #pragma unroll
                for (int j = 0; j < 4; j++) acc[i][j] = 0ull;

            #pragma unroll 4
            for (int d4 = 0; d4 < 16; d4++) {
                ulonglong2 qp[4];
                #pragma unroll
                for (int i = 0; i < 4; i++)
                    qp[i] = *(ulonglong2*)&Qs[(ty + 16 * i) * STRIDE + d4 * 4];
                #pragma unroll
                for (int j = 0; j < 4; j++) {
                    ulonglong2 kp = *(ulonglong2*)&Ks[(tx + 16 * j) * STRIDE + d4 * 4];
                    #pragma unroll
                    for (int i = 0; i < 4; i++) {
                        acc[i][j] = fma2(qp[i].x, kp.x, acc[i][j]);
                        acc[i][j] = fma2(qp[i].y, kp.y, acc[i][j]);
                    }
                }
            }

            // mask + exp2, partial l (unstable ghost-softmax, validated r5)
            float pr[4][4];
            #pragma unroll
            for (int i = 0; i < 4; i++) {
                int rg = q0 + ty + 16 * i;
                #pragma unroll
                for (int j = 0; j < 4; j++) {
                    float2 f = unpack2(acc[i][j]);
                    float s = f.x + f.y;
                    int cg = kt + tx + 16 * j;
                    bool in = (cg >= st[i]) & (cg <= rg);
                    pr[i][j] = in ? ex2f(s) : 0.f;
                }
                l[i] += (pr[i][0] + pr[i][1]) + (pr[i][2] + pr[i][3]);
            }

            // store P row-permuted. P produce/consume is WARP-LOCAL:
            // writer of (col k, slot ty*4+i) is (ty, k&15); reader is (ty, tx).
            #pragma unroll
            for (int j = 0; j < 4; j++) {
                float4 wv = make_float4(pr[0][j], pr[1][j], pr[2][j], pr[3][j]);
                *(float4*)&Ps[(tx + 16 * j) * STRIDE + ty * 4] = wv;
            }
            __syncwarp();      // warp-scope: P visible to warp-mates

            // prefetch next tile into buf^1 (safe: all threads past top barrier)
            if (kt + BC <= q0) {
                u32 kd = kv_s + (u32)((buf ^ 1) * (2 * TILE) * 4);
                u32 vd = kd + TILE * 4;
                #pragma unroll
                for (int u = 0; u < 4; u++) {
                    u32 off = (u32)(cr[u] * STRIDE + cc4 * 4) * 4;
                    cp16(kd + off, &Kb[(long)(kt + BC + cr[u]) * D_ + cc4 * 4]);
                    cp16(vd + off, &Vb[(long)(kt + BC + cr[u]) * D_ + cc4 * 4]);
                }
                CP_COMMIT();
            }

            // PV: per key, 2 LDS.128 + 4 MOV + 8 FFMA2
            #pragma unroll 8
            for (int k = 0; k < BC; k++) {
                float4 pf = *(float4*)&Ps[k * STRIDE + ty * 4];
                ulonglong2 vf = *(ulonglong2*)&Vs[k * STRIDE + tx * 4];
                ull pb0 = pack2(pf.x, pf.x);
                ull pb1 = pack2(pf.y, pf.y);
                ull pb2 = pack2(pf.z, pf.z);
                ull pb3 = pack2(pf.w, pf.w);
                oacc[0][0] = fma2(pb0, vf.x, oacc[0][0]);
                oacc[0][1] = fma2(pb0, vf.y, oacc[0][1]);
                oacc[1][0] = fma2(pb1, vf.x, oacc[1][0]);
                oacc[1][1] = fma2(pb1, vf.y, oacc[1][1]);
                oacc[2][0] = fma2(pb2, vf.x, oacc[2][0]);
                oacc[2][1] = fma2(pb2, vf.y, oacc[2][1]);
                oacc[3][0] = fma2(pb3, vf.x, oacc[3][0]);
                oacc[3][1] = fma2(pb3, vf.y, oacc[3][1]);
            }
        }

        // epilogue: l reduce over 16 lanes per row; contiguous float4 out
        #pragma unroll
        for (int i = 0; i < 4; i++) {
            float ls = l[i];
            #pragma unroll
            for (int off = 1; off < 16; off <<= 1)
                ls += __shfl_xor_sync(0xffffffffu, ls, off);
            float inv = 1.f / ls;
            int row = q0 + ty + 16 * i;
            float* op = (float*)O + base + (long)row * D_ + 4 * tx;
            float2 o0 = unpack2(oacc[i][0]);
            float2 o1 = unpack2(oacc[i][1]);
            *(float4*)op = make_float4(o0.x * inv, o0.y * inv, o1.x * inv, o1.y * inv);
        }
    }
}

extern "C" void kernel_launch(void* const* d_in, const int* in_sizes, int n_in,
                              void* d_out, int out_size) {
    const float* q  = (const float*)d_in[0];
    const float* k  = (const float*)d_in[1];
    const float* v  = (const float*)d_in[2];
    const int* bids = (const int*)d_in[3];
    float* out      = (float*)d_out;

    segstart_kernel<<<(B_ * S_ + 255) / 256, 256>>>(bids);

    const int smem_bytes = 6 * BC * STRIDE * (int)sizeof(float);  // 104448
    cudaFuncSetAttribute(attn_kernel, cudaFuncAttributeMaxDynamicSharedMemorySize,
                         smem_bytes);
    attn_kernel<<<NCTAS, NT, smem_bytes>>>(q, k, v, out);
}